// round 16
// baseline (speedup 1.0000x reference)
#include <cuda_runtime.h>
#include <cuda_fp16.h>
#include <cstdint>

// Problem constants
#define BATCH 8
#define CI    64
#define CO    128
#define HH    128
#define WW    128
#define HW    (HH*WW)          // 16384

// Scratch: y = conv1x1(x), PIXEL-MAJOR, fp16: y[b][p][c]. 32 MiB.
__device__ __half g_y[BATCH * HW * CO];

// ---- packed f32x2 helpers (Blackwell FFMA2) --------------------------------
__device__ __forceinline__ unsigned long long pk2(float a, float b) {
    unsigned long long r;
    asm("mov.b64 %0, {%1, %2};" : "=l"(r) : "f"(a), "f"(b));
    return r;
}
__device__ __forceinline__ void fma2(unsigned long long& d,
                                     unsigned long long a,
                                     unsigned long long b) {
    asm("fma.rn.f32x2 %0, %1, %2, %0;" : "+l"(d) : "l"(a), "l"(b));
}
__device__ __forceinline__ void upk2(float& a, float& b, unsigned long long v) {
    asm("mov.b64 {%0, %1}, %2;" : "=f"(a), "=f"(b) : "l"(v));
}

// ---- fp16 helpers -----------------------------------------------------------
__device__ __forceinline__ __half2 u2h(uint32_t u) {
    return *reinterpret_cast<__half2*>(&u);
}
__device__ __forceinline__ float dot4h(uint2 a, uint2 b) {
    __half2 p = __hmul2(u2h(a.x), u2h(b.x));
    p = __hfma2(u2h(a.y), u2h(b.y), p);
    float2 f = __half22float2(p);
    return f.x + f.y;
}

// ---------------------------------------------------------------------------
// Kernel 1: 1x1 conv, FFMA2 GEMM (proven R12 core) — batch-chunked.
// ---------------------------------------------------------------------------
__global__ void __launch_bounds__(256) conv1x1_kernel(const float* __restrict__ x,
                                                      const float* __restrict__ Wc,
                                                      const float* __restrict__ bc,
                                                      int b0)
{
    extern __shared__ float sm[];
    float* Ws = sm;            // [i][o] 64*128 (Wc transposed)
    float* Xs = sm + 64 * 128; // [i][p] 64*128

    const int b   = b0 + blockIdx.y;
    const int p0  = blockIdx.x * 128;
    const int tid = threadIdx.x;

    for (int idx = tid; idx < 64 * 128; idx += 256) {
        int i = idx >> 7;
        int o = idx & 127;
        Ws[idx] = Wc[o * CI + i];
    }
    {
        const float4* xb4 = reinterpret_cast<const float4*>(x + (size_t)b * CI * HW);
        float4* Xs4 = reinterpret_cast<float4*>(Xs);
        for (int idx = tid; idx < 2048; idx += 256) {
            int i  = idx >> 5;
            int p4 = idx & 31;
            Xs4[idx] = xb4[i * (HW / 4) + (p0 >> 2) + p4];
        }
    }
    __syncthreads();

    const int tx = tid & 15;   // channel group
    const int ty = tid >> 4;   // pixel group

    unsigned long long acc2[4][8];
#pragma unroll
    for (int q = 0; q < 4; ++q)
#pragma unroll
        for (int k = 0; k < 8; ++k) acc2[q][k] = 0ull;

    const float4* Ws4 = reinterpret_cast<const float4*>(Ws);

#pragma unroll 4
    for (int i = 0; i < 64; ++i) {
        float4 w0 = Ws4[i * 32 + tx];
        float4 w1 = Ws4[i * 32 + 16 + tx];

        const float* xrow = Xs + i * 128;
        ulonglong2 xa = *reinterpret_cast<const ulonglong2*>(xrow + ty * 8);
        ulonglong2 xb = *reinterpret_cast<const ulonglong2*>(xrow + ty * 8 + 4);
        unsigned long long xp[4] = {xa.x, xa.y, xb.x, xb.y};

        unsigned long long wd[8];
        wd[0] = pk2(w0.x, w0.x); wd[1] = pk2(w0.y, w0.y);
        wd[2] = pk2(w0.z, w0.z); wd[3] = pk2(w0.w, w0.w);
        wd[4] = pk2(w1.x, w1.x); wd[5] = pk2(w1.y, w1.y);
        wd[6] = pk2(w1.z, w1.z); wd[7] = pk2(w1.w, w1.w);

#pragma unroll
        for (int q = 0; q < 4; ++q)
#pragma unroll
            for (int k = 0; k < 8; ++k)
                fma2(acc2[q][k], xp[q], wd[k]);
    }

    float bv[8];
#pragma unroll
    for (int k = 0; k < 4; ++k) {
        bv[k]     = bc[tx * 4 + k];
        bv[k + 4] = bc[64 + tx * 4 + k];
    }

    __half* yb = g_y + ((size_t)b * HW + p0) * CO;
#pragma unroll
    for (int q = 0; q < 4; ++q) {
#pragma unroll
        for (int half = 0; half < 2; ++half) {
            float e[8];
#pragma unroll
            for (int k = 0; k < 8; ++k) {
                float lo, hi;
                upk2(lo, hi, acc2[q][k]);
                e[k] = (half == 0 ? lo : hi) + bv[k];
            }
            __half* dst = yb + (size_t)(ty * 8 + q * 2 + half) * CO;
            __half2 h0 = __floats2half2_rn(e[0], e[1]);
            __half2 h1 = __floats2half2_rn(e[2], e[3]);
            __half2 h2 = __floats2half2_rn(e[4], e[5]);
            __half2 h3 = __floats2half2_rn(e[6], e[7]);
            *reinterpret_cast<uint2*>(dst + tx * 4) =
                make_uint2(*reinterpret_cast<uint32_t*>(&h0),
                           *reinterpret_cast<uint32_t*>(&h1));
            *reinterpret_cast<uint2*>(dst + 64 + tx * 4) =
                make_uint2(*reinterpret_cast<uint32_t*>(&h2),
                           *reinterpret_cast<uint32_t*>(&h3));
        }
    }
}

// ---------------------------------------------------------------------------
// Kernel 2: 3x3 local attention, warp per 2x2 block, fp16 arithmetic (R14) —
// batch-chunked.
// ---------------------------------------------------------------------------
__global__ void __launch_bounds__(256, 3) attn3x3_kernel(float* __restrict__ out,
                                                         int b0)
{
    __shared__ float    so[32 * CO];     // [px(row*16+col)][c]  16KB
    __shared__ uint32_t wsm[8][4][12];   // [warp][pixel][9 weights as half2-dup]

    const int tid  = threadIdx.x;
    const int wid  = tid >> 5;
    const int lane = tid & 31;

    const int b  = b0 + blockIdx.z;
    const int r0 = blockIdx.y * 2;
    const int wc = blockIdx.x * 16;
    const int c0 = wc + wid * 2;

    const __half* ybase = g_y + ((size_t)b * HW) * CO + lane * 4;

    uint2 vh[4][4];
#pragma unroll
    for (int r = 0; r < 4; ++r) {
        int gh = r0 - 1 + r;
#pragma unroll
        for (int c = 0; c < 4; ++c) {
            int gw = c0 - 1 + c;
            if ((unsigned)gh < HH && (unsigned)gw < WW) {
                vh[r][c] = *reinterpret_cast<const uint2*>(
                    ybase + (size_t)(gh * WW + gw) * CO);
            } else {
                vh[r][c] = make_uint2(0u, 0u);
            }
        }
    }

    const float scale = 0.08838834764831845f; // 1/sqrt(128)
    const bool loHalf = lane < 16;
    const int  q8     = (lane >> 3) & 3;

    float s[9];
#pragma unroll
    for (int n = 0; n < 9; ++n) {
        const int di = n / 3, dj = n % 3;
        float sA = dot4h(vh[di][dj],         vh[1][1]);
        float sB = dot4h(vh[di][dj + 1],     vh[1][2]);
        float sC = dot4h(vh[di + 1][dj],     vh[2][1]);
        float sD = dot4h(vh[di + 1][dj + 1], vh[2][2]);
        float fA = sA + __shfl_xor_sync(0xffffffffu, sA, 16);
        float fB = sB + __shfl_xor_sync(0xffffffffu, sB, 16);
        float fC = sC + __shfl_xor_sync(0xffffffffu, sC, 16);
        float fD = sD + __shfl_xor_sync(0xffffffffu, sD, 16);
        float sLo = loHalf ? fA : fC;
        float sHi = loHalf ? fB : fD;
        float gLo = sLo + __shfl_xor_sync(0xffffffffu, sLo, 8);
        float gHi = sHi + __shfl_xor_sync(0xffffffffu, sHi, 8);
        s[n] = (lane & 8) ? gHi : gLo;
    }
#pragma unroll
    for (int off = 4; off > 0; off >>= 1) {
#pragma unroll
        for (int n = 0; n < 9; ++n)
            s[n] += __shfl_xor_sync(0xffffffffu, s[n], off);
    }

    float a[9], den = 0.f;
#pragma unroll
    for (int n = 0; n < 9; ++n) {
        a[n] = __expf(s[n] * scale);
        den += a[n];
    }
    float inv = 1.0f / den;

    if ((lane & 7) == 0) {
#pragma unroll
        for (int n = 0; n < 9; ++n) {
            __half2 hd = __half2half2(__float2half_rn(a[n] * inv));
            wsm[wid][q8][n] = *reinterpret_cast<uint32_t*>(&hd);
        }
    }
    __syncwarp(0xffffffffu);

    __half2 accx[4], accy[4];
#pragma unroll
    for (int p = 0; p < 4; ++p) {
        accx[p] = __half2half2(__ushort_as_half(0));
        accy[p] = accx[p];
    }
#pragma unroll
    for (int n = 0; n < 9; ++n) {
        const int di = n / 3, dj = n % 3;
        const __half2 wA = u2h(wsm[wid][0][n]);
        const __half2 wB = u2h(wsm[wid][1][n]);
        const __half2 wC = u2h(wsm[wid][2][n]);
        const __half2 wD = u2h(wsm[wid][3][n]);
        const uint2 qa = vh[di][dj];
        const uint2 qb = vh[di][dj + 1];
        const uint2 qc = vh[di + 1][dj];
        const uint2 qd = vh[di + 1][dj + 1];
        accx[0] = __hfma2(wA, u2h(qa.x), accx[0]);
        accy[0] = __hfma2(wA, u2h(qa.y), accy[0]);
        accx[1] = __hfma2(wB, u2h(qb.x), accx[1]);
        accy[1] = __hfma2(wB, u2h(qb.y), accy[1]);
        accx[2] = __hfma2(wC, u2h(qc.x), accx[2]);
        accy[2] = __hfma2(wC, u2h(qc.y), accy[2]);
        accx[3] = __hfma2(wD, u2h(qd.x), accx[3]);
        accy[3] = __hfma2(wD, u2h(qd.y), accy[3]);
    }

    {
        const int colA = wid * 2;
#pragma unroll
        for (int p = 0; p < 4; ++p) {
            float2 fx = __half22float2(accx[p]);
            float2 fy = __half22float2(accy[p]);
            float4 o = make_float4(fx.x, fx.y, fy.x, fy.y);
            int px = (p >> 1) * 16 + colA + (p & 1);
            *reinterpret_cast<float4*>(&so[px * CO + lane * 4]) = o;
        }
    }
    __syncthreads();

    {
        const int c    = tid >> 1;
        const int part = tid & 1;
        float* dst = out + ((size_t)b * CO + c) * HW + r0 * WW + wc + part * 8;
#pragma unroll
        for (int row = 0; row < 2; ++row) {
#pragma unroll
            for (int q = 0; q < 2; ++q) {
                int col = part * 8 + q * 4;
                float4 r;
                r.x = so[(row * 16 + col + 0) * CO + c];
                r.y = so[(row * 16 + col + 1) * CO + c];
                r.z = so[(row * 16 + col + 2) * CO + c];
                r.w = so[(row * 16 + col + 3) * CO + c];
                *reinterpret_cast<float4*>(dst + row * WW + q * 4) = r;
            }
        }
    }
}

// ---------------------------------------------------------------------------
// Host: TWO non-default streams; proper fork/join so conv chain (s1) and
// attn chain (s2) have NO legacy-stream false dependencies. conv_{c+1}
// overlaps attn_c. Falls back to sequential if resource creation failed.
// ---------------------------------------------------------------------------
#define NCHUNK 4   // chunks of 2 batches

namespace {
struct PipeRes {
    cudaStream_t s1 = nullptr, s2 = nullptr;
    cudaEvent_t  ev0 = nullptr;          // fork
    cudaEvent_t  evC[NCHUNK] = {};       // conv chunk done
    cudaEvent_t  evJoin = nullptr;       // join
    bool ok = false;
    PipeRes() {
        ok =  (cudaStreamCreateWithFlags(&s1, cudaStreamNonBlocking) == cudaSuccess)
           && (cudaStreamCreateWithFlags(&s2, cudaStreamNonBlocking) == cudaSuccess)
           && (cudaEventCreateWithFlags(&ev0, cudaEventDisableTiming) == cudaSuccess)
           && (cudaEventCreateWithFlags(&evJoin, cudaEventDisableTiming) == cudaSuccess);
        for (int i = 0; i < NCHUNK && ok; ++i)
            ok = (cudaEventCreateWithFlags(&evC[i], cudaEventDisableTiming)
                  == cudaSuccess);
    }
};
PipeRes g_pipe;
}

extern "C" void kernel_launch(void* const* d_in, const int* in_sizes, int n_in,
                              void* d_out, int out_size)
{
    const float* x  = nullptr;
    const float* Wc = nullptr;
    const float* bc = nullptr;
    for (int i = 0; i < n_in; ++i) {
        if (in_sizes[i] == BATCH * CI * HW) x  = (const float*)d_in[i];
        else if (in_sizes[i] == CO * CI)    Wc = (const float*)d_in[i];
        else if (in_sizes[i] == CO)         bc = (const float*)d_in[i];
    }
    float* out = (float*)d_out;

    static const int conv_smem = 64 * 128 * 2 * sizeof(float);   // 65536

    cudaFuncSetAttribute(conv1x1_kernel,
                         cudaFuncAttributeMaxDynamicSharedMemorySize, conv_smem);

    const dim3 convGrid(HW / 128, BATCH / NCHUNK);          // 128 x 2
    const dim3 attnGrid(WW / 16, HH / 2, BATCH / NCHUNK);   // 8 x 64 x 2

    if (g_pipe.ok) {
        // Fork from capture-origin stream (0) into s1 (conv) and s2 (attn).
        cudaEventRecord(g_pipe.ev0, 0);
        cudaStreamWaitEvent(g_pipe.s1, g_pipe.ev0, 0);
        cudaStreamWaitEvent(g_pipe.s2, g_pipe.ev0, 0);

        for (int c = 0; c < NCHUNK; ++c) {
            conv1x1_kernel<<<convGrid, 256, conv_smem, g_pipe.s1>>>(
                x, Wc, bc, c * (BATCH / NCHUNK));
            cudaEventRecord(g_pipe.evC[c], g_pipe.s1);
            cudaStreamWaitEvent(g_pipe.s2, g_pipe.evC[c], 0);
            attn3x3_kernel<<<attnGrid, 256, 0, g_pipe.s2>>>(
                out, c * (BATCH / NCHUNK));
        }
        // Join: attn chain transitively covers conv chain (attn3 waits conv3).
        cudaEventRecord(g_pipe.evJoin, g_pipe.s2);
        cudaStreamWaitEvent(0, g_pipe.evJoin, 0);
    } else {
        // Fallback: sequential on default stream.
        for (int c = 0; c < NCHUNK; ++c)
            conv1x1_kernel<<<convGrid, 256, conv_smem>>>(x, Wc, bc,
                                                         c * (BATCH / NCHUNK));
        for (int c = 0; c < NCHUNK; ++c)
            attn3x3_kernel<<<attnGrid, 256>>>(out, c * (BATCH / NCHUNK));
    }
}

// round 17
// speedup vs baseline: 1.1723x; 1.1723x over previous
#include <cuda_runtime.h>
#include <cuda_fp16.h>
#include <cstdint>

// Problem constants
#define BATCH 8
#define CI    64
#define CO    128
#define HH    128
#define WW    128
#define HW    (HH*WW)          // 16384

// Scratch: y = conv1x1(x), PIXEL-MAJOR, fp16: y[b][p][c]. 32 MiB.
__device__ __half g_y[BATCH * HW * CO];

// ---- packed f32x2 helpers (Blackwell FFMA2) --------------------------------
__device__ __forceinline__ unsigned long long pk2(float a, float b) {
    unsigned long long r;
    asm("mov.b64 %0, {%1, %2};" : "=l"(r) : "f"(a), "f"(b));
    return r;
}
__device__ __forceinline__ void fma2(unsigned long long& d,
                                     unsigned long long a,
                                     unsigned long long b) {
    asm("fma.rn.f32x2 %0, %1, %2, %0;" : "+l"(d) : "l"(a), "l"(b));
}
__device__ __forceinline__ void upk2(float& a, float& b, unsigned long long v) {
    asm("mov.b64 {%0, %1}, %2;" : "=f"(a), "=f"(b) : "l"(v));
}

// ---- fp16 helpers -----------------------------------------------------------
__device__ __forceinline__ __half2 u2h(uint32_t u) {
    return *reinterpret_cast<__half2*>(&u);
}
__device__ __forceinline__ float dot4h(uint2 a, uint2 b) {
    __half2 p = __hmul2(u2h(a.x), u2h(b.x));
    p = __hfma2(u2h(a.y), u2h(b.y), p);
    float2 f = __half22float2(p);
    return f.x + f.y;
}

// ---------------------------------------------------------------------------
// Kernel 1: 1x1 conv, FFMA2 GEMM, 512 threads/CTA (8px x 4ch per thread).
// Same 128px x 128ch CTA tile as before, half the regs/thread -> 2 CTAs/SM
// = 32 warps/SM (vs 16) for latency hiding.
// ---------------------------------------------------------------------------
__global__ void __launch_bounds__(512, 2) conv1x1_kernel(const float* __restrict__ x,
                                                         const float* __restrict__ Wc,
                                                         const float* __restrict__ bc)
{
    extern __shared__ float sm[];
    float* Ws = sm;            // [i][o] 64*128 (Wc transposed)
    float* Xs = sm + 64 * 128; // [i][p] 64*128

    const int b   = blockIdx.y;
    const int p0  = blockIdx.x * 128;
    const int tid = threadIdx.x;

    for (int idx = tid; idx < 64 * 128; idx += 512) {
        int i = idx >> 7;
        int o = idx & 127;
        Ws[idx] = Wc[o * CI + i];
    }
    {
        const float4* xb4 = reinterpret_cast<const float4*>(x + (size_t)b * CI * HW);
        float4* Xs4 = reinterpret_cast<float4*>(Xs);
        for (int idx = tid; idx < 2048; idx += 512) {
            int i  = idx >> 5;
            int p4 = idx & 31;
            Xs4[idx] = xb4[i * (HW / 4) + (p0 >> 2) + p4];
        }
    }
    __syncthreads();

    const int tx = tid & 31;   // channel group: channels tx*4..tx*4+3
    const int ty = tid >> 5;   // pixel group:   pixels  ty*8..ty*8+7

    // acc2[q][k]: pixel-pair q (pixels 2q,2q+1 of this thread's 8), channel k
    unsigned long long acc2[4][4];
#pragma unroll
    for (int q = 0; q < 4; ++q)
#pragma unroll
        for (int k = 0; k < 4; ++k) acc2[q][k] = 0ull;

    const float4* Ws4 = reinterpret_cast<const float4*>(Ws);

#pragma unroll 4
    for (int i = 0; i < 64; ++i) {
        float4 w0 = Ws4[i * 32 + tx];          // 4 channels (per-lane distinct)

        // x: broadcast LDS.128; adjacent floats ARE packed f32x2 pairs
        const float* xrow = Xs + i * 128;
        ulonglong2 xa = *reinterpret_cast<const ulonglong2*>(xrow + ty * 8);
        ulonglong2 xb = *reinterpret_cast<const ulonglong2*>(xrow + ty * 8 + 4);
        unsigned long long xp[4] = {xa.x, xa.y, xb.x, xb.y};

        unsigned long long wd[4];
        wd[0] = pk2(w0.x, w0.x); wd[1] = pk2(w0.y, w0.y);
        wd[2] = pk2(w0.z, w0.z); wd[3] = pk2(w0.w, w0.w);

#pragma unroll
        for (int q = 0; q < 4; ++q)
#pragma unroll
            for (int k = 0; k < 4; ++k)
                fma2(acc2[q][k], xp[q], wd[k]);
    }

    float bv[4];
#pragma unroll
    for (int k = 0; k < 4; ++k) bv[k] = bc[tx * 4 + k];

    __half* yb = g_y + ((size_t)b * HW + p0) * CO;
#pragma unroll
    for (int q = 0; q < 4; ++q) {
#pragma unroll
        for (int half = 0; half < 2; ++half) {
            float e[4];
#pragma unroll
            for (int k = 0; k < 4; ++k) {
                float lo, hi;
                upk2(lo, hi, acc2[q][k]);
                e[k] = (half == 0 ? lo : hi) + bv[k];
            }
            __half* dst = yb + (size_t)(ty * 8 + q * 2 + half) * CO + tx * 4;
            __half2 h0 = __floats2half2_rn(e[0], e[1]);
            __half2 h1 = __floats2half2_rn(e[2], e[3]);
            *reinterpret_cast<uint2*>(dst) =
                make_uint2(*reinterpret_cast<uint32_t*>(&h0),
                           *reinterpret_cast<uint32_t*>(&h1));
        }
    }
}

// ---------------------------------------------------------------------------
// Kernel 2: 3x3 local attention, warp per 2x2 block, fp16 arithmetic
// (R14 best-known, unchanged).
// ---------------------------------------------------------------------------
__global__ void __launch_bounds__(256, 3) attn3x3_kernel(float* __restrict__ out)
{
    __shared__ float    so[32 * CO];     // [px(row*16+col)][c]  16KB
    __shared__ uint32_t wsm[8][4][12];   // [warp][pixel][9 weights as half2-dup]

    const int tid  = threadIdx.x;
    const int wid  = tid >> 5;
    const int lane = tid & 31;

    const int b  = blockIdx.z;
    const int r0 = blockIdx.y * 2;
    const int wc = blockIdx.x * 16;
    const int c0 = wc + wid * 2;

    const __half* ybase = g_y + ((size_t)b * HW) * CO + lane * 4;

    uint2 vh[4][4];
#pragma unroll
    for (int r = 0; r < 4; ++r) {
        int gh = r0 - 1 + r;
#pragma unroll
        for (int c = 0; c < 4; ++c) {
            int gw = c0 - 1 + c;
            if ((unsigned)gh < HH && (unsigned)gw < WW) {
                vh[r][c] = *reinterpret_cast<const uint2*>(
                    ybase + (size_t)(gh * WW + gw) * CO);
            } else {
                vh[r][c] = make_uint2(0u, 0u);
            }
        }
    }

    const float scale = 0.08838834764831845f; // 1/sqrt(128)
    const bool loHalf = lane < 16;
    const int  q8     = (lane >> 3) & 3;

    float s[9];
#pragma unroll
    for (int n = 0; n < 9; ++n) {
        const int di = n / 3, dj = n % 3;
        float sA = dot4h(vh[di][dj],         vh[1][1]);
        float sB = dot4h(vh[di][dj + 1],     vh[1][2]);
        float sC = dot4h(vh[di + 1][dj],     vh[2][1]);
        float sD = dot4h(vh[di + 1][dj + 1], vh[2][2]);
        float fA = sA + __shfl_xor_sync(0xffffffffu, sA, 16);
        float fB = sB + __shfl_xor_sync(0xffffffffu, sB, 16);
        float fC = sC + __shfl_xor_sync(0xffffffffu, sC, 16);
        float fD = sD + __shfl_xor_sync(0xffffffffu, sD, 16);
        float sLo = loHalf ? fA : fC;
        float sHi = loHalf ? fB : fD;
        float gLo = sLo + __shfl_xor_sync(0xffffffffu, sLo, 8);
        float gHi = sHi + __shfl_xor_sync(0xffffffffu, sHi, 8);
        s[n] = (lane & 8) ? gHi : gLo;
    }
#pragma unroll
    for (int off = 4; off > 0; off >>= 1) {
#pragma unroll
        for (int n = 0; n < 9; ++n)
            s[n] += __shfl_xor_sync(0xffffffffu, s[n], off);
    }

    float a[9], den = 0.f;
#pragma unroll
    for (int n = 0; n < 9; ++n) {
        a[n] = __expf(s[n] * scale);
        den += a[n];
    }
    float inv = 1.0f / den;

    if ((lane & 7) == 0) {
#pragma unroll
        for (int n = 0; n < 9; ++n) {
            __half2 hd = __half2half2(__float2half_rn(a[n] * inv));
            wsm[wid][q8][n] = *reinterpret_cast<uint32_t*>(&hd);
        }
    }
    __syncwarp(0xffffffffu);

    __half2 accx[4], accy[4];
#pragma unroll
    for (int p = 0; p < 4; ++p) {
        accx[p] = __half2half2(__ushort_as_half(0));
        accy[p] = accx[p];
    }
#pragma unroll
    for (int n = 0; n < 9; ++n) {
        const int di = n / 3, dj = n % 3;
        const __half2 wA = u2h(wsm[wid][0][n]);
        const __half2 wB = u2h(wsm[wid][1][n]);
        const __half2 wC = u2h(wsm[wid][2][n]);
        const __half2 wD = u2h(wsm[wid][3][n]);
        const uint2 qa = vh[di][dj];
        const uint2 qb = vh[di][dj + 1];
        const uint2 qc = vh[di + 1][dj];
        const uint2 qd = vh[di + 1][dj + 1];
        accx[0] = __hfma2(wA, u2h(qa.x), accx[0]);
        accy[0] = __hfma2(wA, u2h(qa.y), accy[0]);
        accx[1] = __hfma2(wB, u2h(qb.x), accx[1]);
        accy[1] = __hfma2(wB, u2h(qb.y), accy[1]);
        accx[2] = __hfma2(wC, u2h(qc.x), accx[2]);
        accy[2] = __hfma2(wC, u2h(qc.y), accy[2]);
        accx[3] = __hfma2(wD, u2h(qd.x), accx[3]);
        accy[3] = __hfma2(wD, u2h(qd.y), accy[3]);
    }

    {
        const int colA = wid * 2;
#pragma unroll
        for (int p = 0; p < 4; ++p) {
            float2 fx = __half22float2(accx[p]);
            float2 fy = __half22float2(accy[p]);
            float4 o = make_float4(fx.x, fx.y, fy.x, fy.y);
            int px = (p >> 1) * 16 + colA + (p & 1);
            *reinterpret_cast<float4*>(&so[px * CO + lane * 4]) = o;
        }
    }
    __syncthreads();

    {
        const int c    = tid >> 1;
        const int part = tid & 1;
        float* dst = out + ((size_t)b * CO + c) * HW + r0 * WW + wc + part * 8;
#pragma unroll
        for (int row = 0; row < 2; ++row) {
#pragma unroll
            for (int q = 0; q < 2; ++q) {
                int col = part * 8 + q * 4;
                float4 r;
                r.x = so[(row * 16 + col + 0) * CO + c];
                r.y = so[(row * 16 + col + 1) * CO + c];
                r.z = so[(row * 16 + col + 2) * CO + c];
                r.w = so[(row * 16 + col + 3) * CO + c];
                *reinterpret_cast<float4*>(dst + row * WW + q * 4) = r;
            }
        }
    }
}

// ---------------------------------------------------------------------------
extern "C" void kernel_launch(void* const* d_in, const int* in_sizes, int n_in,
                              void* d_out, int out_size)
{
    const float* x  = nullptr;
    const float* Wc = nullptr;
    const float* bc = nullptr;
    for (int i = 0; i < n_in; ++i) {
        if (in_sizes[i] == BATCH * CI * HW) x  = (const float*)d_in[i];
        else if (in_sizes[i] == CO * CI)    Wc = (const float*)d_in[i];
        else if (in_sizes[i] == CO)         bc = (const float*)d_in[i];
    }
    float* out = (float*)d_out;

    static const int conv_smem = 64 * 128 * 2 * sizeof(float);   // 65536

    cudaFuncSetAttribute(conv1x1_kernel,
                         cudaFuncAttributeMaxDynamicSharedMemorySize, conv_smem);

    conv1x1_kernel<<<dim3(HW / 128, BATCH), 512, conv_smem>>>(x, Wc, bc);
    attn3x3_kernel<<<dim3(WW / 16, HH / 2, BATCH), 256>>>(out);
}